// round 1
// baseline (speedup 1.0000x reference)
#include <cuda_runtime.h>
#include <math.h>

#define B_    16
#define C_    256
#define S_    1024
#define NH    4
#define DK    64
#define SCALE 0.125f

// -------- scratch (no cudaMalloc allowed) --------
__device__ float g_q  [(size_t)B_ * NH * S_ * DK];   // [B,H,S,D]
__device__ float g_k  [(size_t)B_ * NH * S_ * DK];
__device__ float g_v  [(size_t)B_ * NH * S_ * DK];
__device__ float g_res[(size_t)B_ * S_ * C_];        // [B,S,C] attention output

// ============================================================
// Kernel A: QKV = xs @ w_qkv + b_qkv, scattered to Q/K/V
// xs[b,s,c] = x[b,c,s].  M=16384 (b,s), K=256 (c), N=768.
// ============================================================
__global__ void qkv_gemm(const float* __restrict__ x,
                         const float* __restrict__ w,
                         const float* __restrict__ bias)
{
    __shared__ float As[16][64];   // [k][m]
    __shared__ float Bs[16][64];   // [k][n]

    const int mBase = blockIdx.y * 64;
    const int nBase = blockIdx.x * 64;
    const int tid = threadIdx.x;           // 256 threads
    const int tx = tid & 15, ty = tid >> 4;

    const int b  = mBase >> 10;            // 64-row tile never crosses a batch
    const int s0 = mBase & 1023;

    float acc[4][4] = {};

    for (int k0 = 0; k0 < C_; k0 += 16) {
        {   // A tile: x[b, k0+kk, s0+mi] -> As[kk][mi]  (coalesced over mi)
            int e  = tid * 4;
            int kk = e >> 6, mi = e & 63;
            const float* xp = x + ((size_t)b * C_ + (k0 + kk)) * S_ + s0 + mi;
            *reinterpret_cast<float4*>(&As[kk][mi]) =
                *reinterpret_cast<const float4*>(xp);
        }
        {   // B tile: w[k0+kk, nBase+ni] -> Bs[kk][ni]
            int e  = tid * 4;
            int kk = e >> 6, ni = e & 63;
            const float* wp = w + (size_t)(k0 + kk) * 768 + nBase + ni;
            *reinterpret_cast<float4*>(&Bs[kk][ni]) =
                *reinterpret_cast<const float4*>(wp);
        }
        __syncthreads();
        #pragma unroll
        for (int kk = 0; kk < 16; ++kk) {
            float a[4], bb[4];
            *reinterpret_cast<float4*>(a)  = *reinterpret_cast<const float4*>(&As[kk][ty * 4]);
            *reinterpret_cast<float4*>(bb) = *reinterpret_cast<const float4*>(&Bs[kk][tx * 4]);
            #pragma unroll
            for (int i = 0; i < 4; ++i)
                #pragma unroll
                for (int j = 0; j < 4; ++j)
                    acc[i][j] = fmaf(a[i], bb[j], acc[i][j]);
        }
        __syncthreads();
    }

    // scatter: column col = h*192 + r;  r<64 -> Q, <128 -> K, else V
    #pragma unroll
    for (int j = 0; j < 4; ++j) {
        int col = nBase + tx * 4 + j;
        int h = col / 192, r = col % 192;
        float bv = bias[col];
        float* dst; int t;
        if (r < 64)       { dst = g_q; t = r; }
        else if (r < 128) { dst = g_k; t = r - 64; }
        else              { dst = g_v; t = r - 128; }
        size_t base = ((size_t)(b * NH + h) * S_);
        #pragma unroll
        for (int i = 0; i < 4; ++i) {
            int s = s0 + ty * 4 + i;
            dst[(base + s) * DK + t] = acc[i][j] + bv;
        }
    }
}

// ============================================================
// Kernel B: flash attention.  One CTA per (bh, 64-query block).
// smem tiles are [d or j][m/n]-major so inner loops are float4 LDS.
// ============================================================
#define LDp 68   // row pad (68*4B = 272B, 16B aligned rows)
#define FLASH_SMEM ((4 * 64 * LDp + 3 * 64) * 4)

__global__ void flash_attn()
{
    extern __shared__ float sm[];
    float* Qs  = sm;                 // [d][m]  64 x LDp
    float* Ks  = Qs  + 64 * LDp;     // [d][n]
    float* St  = Ks  + 64 * LDp;     // [j][m]  scores, then probs
    float* Vs  = St  + 64 * LDp;     // [j][d]
    float* mrow = Vs + 64 * LDp;     // [64]
    float* lrow = mrow + 64;
    float* arow = lrow + 64;

    const int tid = threadIdx.x;     // 256
    const int tx = tid & 15, ty = tid >> 4;
    const int bh = blockIdx.y;       // b*NH + h
    const int s0 = blockIdx.x * 64;  // query block
    const int b  = bh >> 2, h = bh & 3;

    // ---- load Q tile transposed: Qs[d][m] ----
    {
        int m  = tid >> 2;
        int d0 = (tid & 3) * 16;
        const float* qp = g_q + ((size_t)bh * S_ + (s0 + m)) * DK + d0;
        #pragma unroll
        for (int q4 = 0; q4 < 4; ++q4) {
            float4 v = *reinterpret_cast<const float4*>(qp + q4 * 4);
            Qs[(d0 + q4 * 4 + 0) * LDp + m] = v.x;
            Qs[(d0 + q4 * 4 + 1) * LDp + m] = v.y;
            Qs[(d0 + q4 * 4 + 2) * LDp + m] = v.z;
            Qs[(d0 + q4 * 4 + 3) * LDp + m] = v.w;
        }
    }
    if (tid < 64) { mrow[tid] = -INFINITY; lrow[tid] = 0.f; }

    float o[4][4] = {};

    for (int j0 = 0; j0 < S_; j0 += 64) {
        __syncthreads();   // prior consumers of Ks/Vs/St done
        {   // K tile transposed: Ks[d][n]
            int n  = tid >> 2;
            int d0 = (tid & 3) * 16;
            const float* kp = g_k + ((size_t)bh * S_ + (j0 + n)) * DK + d0;
            #pragma unroll
            for (int q4 = 0; q4 < 4; ++q4) {
                float4 v = *reinterpret_cast<const float4*>(kp + q4 * 4);
                Ks[(d0 + q4 * 4 + 0) * LDp + n] = v.x;
                Ks[(d0 + q4 * 4 + 1) * LDp + n] = v.y;
                Ks[(d0 + q4 * 4 + 2) * LDp + n] = v.z;
                Ks[(d0 + q4 * 4 + 3) * LDp + n] = v.w;
            }
            // V tile direct: Vs[j][d]
            const float* vp = g_v + ((size_t)bh * S_ + (j0 + n)) * DK + d0;
            #pragma unroll
            for (int q4 = 0; q4 < 4; ++q4)
                *reinterpret_cast<float4*>(&Vs[n * LDp + d0 + q4 * 4]) =
                    *reinterpret_cast<const float4*>(vp + q4 * 4);
        }
        __syncthreads();

        // ---- scores: St[j][m] = (Q K^T)[m][j] * SCALE ----
        {
            float sc[4][4] = {};
            #pragma unroll
            for (int kk = 0; kk < 64; ++kk) {
                float a[4], bb[4];
                *reinterpret_cast<float4*>(a)  = *reinterpret_cast<const float4*>(&Qs[kk * LDp + ty * 4]);
                *reinterpret_cast<float4*>(bb) = *reinterpret_cast<const float4*>(&Ks[kk * LDp + tx * 4]);
                #pragma unroll
                for (int i = 0; i < 4; ++i)
                    #pragma unroll
                    for (int j = 0; j < 4; ++j)
                        sc[i][j] = fmaf(a[i], bb[j], sc[i][j]);
            }
            #pragma unroll
            for (int j = 0; j < 4; ++j) {
                float4 v = make_float4(sc[0][j] * SCALE, sc[1][j] * SCALE,
                                       sc[2][j] * SCALE, sc[3][j] * SCALE);
                *reinterpret_cast<float4*>(&St[(tx * 4 + j) * LDp + ty * 4]) = v;
            }
        }
        __syncthreads();

        // ---- online softmax, one thread per query row ----
        if (tid < 64) {
            int r = tid;
            float mo = mrow[r];
            float mn = mo;
            #pragma unroll 8
            for (int j = 0; j < 64; ++j) mn = fmaxf(mn, St[j * LDp + r]);
            float al = __expf(mo - mn);
            float sum = 0.f;
            #pragma unroll 8
            for (int j = 0; j < 64; ++j) {
                float p = __expf(St[j * LDp + r] - mn);
                St[j * LDp + r] = p;
                sum += p;
            }
            lrow[r] = lrow[r] * al + sum;
            mrow[r] = mn;
            arow[r] = al;
        }
        __syncthreads();

        // ---- O = O*alpha + P @ V ----
        {
            float al[4];
            #pragma unroll
            for (int i = 0; i < 4; ++i) al[i] = arow[ty * 4 + i];
            #pragma unroll
            for (int i = 0; i < 4; ++i)
                #pragma unroll
                for (int j = 0; j < 4; ++j)
                    o[i][j] *= al[i];
            #pragma unroll
            for (int jj = 0; jj < 64; ++jj) {
                float a[4], bb[4];
                *reinterpret_cast<float4*>(a)  = *reinterpret_cast<const float4*>(&St[jj * LDp + ty * 4]);
                *reinterpret_cast<float4*>(bb) = *reinterpret_cast<const float4*>(&Vs[jj * LDp + tx * 4]);
                #pragma unroll
                for (int i = 0; i < 4; ++i)
                    #pragma unroll
                    for (int j = 0; j < 4; ++j)
                        o[i][j] = fmaf(a[i], bb[j], o[i][j]);
            }
        }
    }

    // ---- normalize + write res[b, s, h*64+d] ----
    #pragma unroll
    for (int i = 0; i < 4; ++i) {
        int s = s0 + ty * 4 + i;
        float inv = 1.0f / lrow[ty * 4 + i];
        float* rp = g_res + ((size_t)b * S_ + s) * C_ + h * 64 + tx * 4;
        float4 v = make_float4(o[i][0] * inv, o[i][1] * inv, o[i][2] * inv, o[i][3] * inv);
        *reinterpret_cast<float4*>(rp) = v;
    }
}

// ============================================================
// Kernel C: out = res @ w_out + b_out + xs, then transpose to [B,C,S]
// M=16384 (b,s), K=256 (hd), N=256 (c)
// ============================================================
__global__ void out_gemm(const float* __restrict__ x,
                         const float* __restrict__ w,
                         const float* __restrict__ bias,
                         float* __restrict__ out)
{
    __shared__ float As[16][68];   // [k][m] transposed
    __shared__ float Bs[16][64];   // [k][n]

    const int mBase = blockIdx.y * 64;
    const int nBase = blockIdx.x * 64;
    const int tid = threadIdx.x;
    const int tx = tid & 15, ty = tid >> 4;

    const int b  = mBase >> 10;
    const int s0 = mBase & 1023;

    float acc[4][4] = {};

    for (int k0 = 0; k0 < C_; k0 += 16) {
        {   // res[m][k] contiguous in k; transpose into As[k][m]
            int mi  = tid >> 2;
            int kk0 = (tid & 3) * 4;
            float4 v = *reinterpret_cast<const float4*>(
                g_res + (size_t)(mBase + mi) * C_ + k0 + kk0);
            As[kk0 + 0][mi] = v.x;
            As[kk0 + 1][mi] = v.y;
            As[kk0 + 2][mi] = v.z;
            As[kk0 + 3][mi] = v.w;
        }
        {
            int e  = tid * 4;
            int kk = e >> 6, ni = e & 63;
            const float* wp = w + (size_t)(k0 + kk) * C_ + nBase + ni;
            *reinterpret_cast<float4*>(&Bs[kk][ni]) =
                *reinterpret_cast<const float4*>(wp);
        }
        __syncthreads();
        #pragma unroll
        for (int kk = 0; kk < 16; ++kk) {
            float a[4], bb[4];
            *reinterpret_cast<float4*>(a)  = *reinterpret_cast<const float4*>(&As[kk][ty * 4]);
            *reinterpret_cast<float4*>(bb) = *reinterpret_cast<const float4*>(&Bs[kk][tx * 4]);
            #pragma unroll
            for (int i = 0; i < 4; ++i)
                #pragma unroll
                for (int j = 0; j < 4; ++j)
                    acc[i][j] = fmaf(a[i], bb[j], acc[i][j]);
        }
        __syncthreads();
    }

    // out[b][c][s] = acc + b_out[c] + x[b][c][s]
    #pragma unroll
    for (int j = 0; j < 4; ++j) {
        int c = nBase + tx * 4 + j;
        float bv = bias[c];
        const float* xp = x + ((size_t)b * C_ + c) * S_;
        float* op = out + ((size_t)b * C_ + c) * S_;
        #pragma unroll
        for (int i = 0; i < 4; ++i) {
            int s = s0 + ty * 4 + i;
            op[s] = acc[i][j] + bv + xp[s];
        }
    }
}

// ============================================================
extern "C" void kernel_launch(void* const* d_in, const int* in_sizes, int n_in,
                              void* d_out, int out_size)
{
    const float* x     = (const float*)d_in[0];
    const float* w_qkv = (const float*)d_in[1];
    const float* b_qkv = (const float*)d_in[2];
    const float* w_out = (const float*)d_in[3];
    const float* b_out = (const float*)d_in[4];
    float* out = (float*)d_out;

    cudaFuncSetAttribute(flash_attn, cudaFuncAttributeMaxDynamicSharedMemorySize,
                         FLASH_SMEM);

    qkv_gemm<<<dim3(768 / 64, (B_ * S_) / 64), 256>>>(x, w_qkv, b_qkv);
    flash_attn<<<dim3(S_ / 64, B_ * NH), 256, FLASH_SMEM>>>();
    out_gemm<<<dim3(C_ / 64, (B_ * S_) / 64), 256>>>(x, w_out, b_out, out);
}

// round 4
// speedup vs baseline: 1.1483x; 1.1483x over previous
#include <cuda_runtime.h>
#include <math.h>

#define B_    16
#define C_    256
#define S_    1024
#define NH    4
#define DK    64
#define SCALE 0.125f

// -------- scratch (no cudaMalloc allowed) --------
__device__ float g_q  [(size_t)B_ * NH * S_ * DK];   // [B,H,S,D]
__device__ float g_k  [(size_t)B_ * NH * S_ * DK];
__device__ float g_v  [(size_t)B_ * NH * S_ * DK];
__device__ float g_res[(size_t)B_ * S_ * C_];        // [B,S,C] attention output

// ============================================================
// Kernel A: QKV = xs @ w_qkv + b_qkv, scattered to Q/K/V
// xs[b,s,c] = x[b,c,s].  M=16384 (b,s), K=256 (c), N=768.
// ============================================================
__global__ void qkv_gemm(const float* __restrict__ x,
                         const float* __restrict__ w,
                         const float* __restrict__ bias)
{
    __shared__ float As[16][64];   // [k][m]
    __shared__ float Bs[16][64];   // [k][n]

    const int mBase = blockIdx.y * 64;
    const int nBase = blockIdx.x * 64;
    const int tid = threadIdx.x;           // 256 threads
    const int tx = tid & 15, ty = tid >> 4;

    const int b  = mBase >> 10;            // 64-row tile never crosses a batch
    const int s0 = mBase & 1023;

    float acc[4][4] = {};

    for (int k0 = 0; k0 < C_; k0 += 16) {
        {   // A tile: x[b, k0+kk, s0+mi] -> As[kk][mi]  (coalesced over mi)
            int e  = tid * 4;
            int kk = e >> 6, mi = e & 63;
            const float* xp = x + ((size_t)b * C_ + (k0 + kk)) * S_ + s0 + mi;
            *reinterpret_cast<float4*>(&As[kk][mi]) =
                *reinterpret_cast<const float4*>(xp);
        }
        {   // B tile: w[k0+kk, nBase+ni] -> Bs[kk][ni]
            int e  = tid * 4;
            int kk = e >> 6, ni = e & 63;
            const float* wp = w + (size_t)(k0 + kk) * 768 + nBase + ni;
            *reinterpret_cast<float4*>(&Bs[kk][ni]) =
                *reinterpret_cast<const float4*>(wp);
        }
        __syncthreads();
        #pragma unroll
        for (int kk = 0; kk < 16; ++kk) {
            float a[4], bb[4];
            *reinterpret_cast<float4*>(a)  = *reinterpret_cast<const float4*>(&As[kk][ty * 4]);
            *reinterpret_cast<float4*>(bb) = *reinterpret_cast<const float4*>(&Bs[kk][tx * 4]);
            #pragma unroll
            for (int i = 0; i < 4; ++i)
                #pragma unroll
                for (int j = 0; j < 4; ++j)
                    acc[i][j] = fmaf(a[i], bb[j], acc[i][j]);
        }
        __syncthreads();
    }

    // scatter: column col = h*192 + r;  r<64 -> Q, <128 -> K, else V
    #pragma unroll
    for (int j = 0; j < 4; ++j) {
        int col = nBase + tx * 4 + j;
        int h = col / 192, r = col % 192;
        float bv = bias[col];
        float* dst; int t;
        if (r < 64)       { dst = g_q; t = r; }
        else if (r < 128) { dst = g_k; t = r - 64; }
        else              { dst = g_v; t = r - 128; }
        size_t base = ((size_t)(b * NH + h) * S_);
        #pragma unroll
        for (int i = 0; i < 4; ++i) {
            int s = s0 + ty * 4 + i;
            dst[(base + s) * DK + t] = acc[i][j] + bv;
        }
    }
}

// ============================================================
// Kernel B: flash attention.  One CTA per (bh, 64-query block).
// smem tiles are [d or j][m/n]-major so inner loops are float4 LDS.
// ============================================================
#define LDp 68   // row pad (68*4B = 272B, 16B aligned rows)
#define FLASH_SMEM ((4 * 64 * LDp + 3 * 64) * 4)

__global__ void flash_attn()
{
    extern __shared__ float sm[];
    float* Qs  = sm;                 // [d][m]  64 x LDp
    float* Ks  = Qs  + 64 * LDp;     // [d][n]
    float* St  = Ks  + 64 * LDp;     // [j][m]  scores, then probs
    float* Vs  = St  + 64 * LDp;     // [j][d]
    float* mrow = Vs + 64 * LDp;     // [64]
    float* lrow = mrow + 64;
    float* arow = lrow + 64;

    const int tid = threadIdx.x;     // 256
    const int tx = tid & 15, ty = tid >> 4;
    const int bh = blockIdx.y;       // b*NH + h
    const int s0 = blockIdx.x * 64;  // query block
    const int b  = bh >> 2, h = bh & 3;

    // ---- load Q tile transposed: Qs[d][m] ----
    {
        int m  = tid >> 2;
        int d0 = (tid & 3) * 16;
        const float* qp = g_q + ((size_t)bh * S_ + (s0 + m)) * DK + d0;
        #pragma unroll
        for (int q4 = 0; q4 < 4; ++q4) {
            float4 v = *reinterpret_cast<const float4*>(qp + q4 * 4);
            Qs[(d0 + q4 * 4 + 0) * LDp + m] = v.x;
            Qs[(d0 + q4 * 4 + 1) * LDp + m] = v.y;
            Qs[(d0 + q4 * 4 + 2) * LDp + m] = v.z;
            Qs[(d0 + q4 * 4 + 3) * LDp + m] = v.w;
        }
    }
    if (tid < 64) { mrow[tid] = -INFINITY; lrow[tid] = 0.f; }

    float o[4][4] = {};

    for (int j0 = 0; j0 < S_; j0 += 64) {
        __syncthreads();   // prior consumers of Ks/Vs/St done
        {   // K tile transposed: Ks[d][n]
            int n  = tid >> 2;
            int d0 = (tid & 3) * 16;
            const float* kp = g_k + ((size_t)bh * S_ + (j0 + n)) * DK + d0;
            #pragma unroll
            for (int q4 = 0; q4 < 4; ++q4) {
                float4 v = *reinterpret_cast<const float4*>(kp + q4 * 4);
                Ks[(d0 + q4 * 4 + 0) * LDp + n] = v.x;
                Ks[(d0 + q4 * 4 + 1) * LDp + n] = v.y;
                Ks[(d0 + q4 * 4 + 2) * LDp + n] = v.z;
                Ks[(d0 + q4 * 4 + 3) * LDp + n] = v.w;
            }
            // V tile direct: Vs[j][d]
            const float* vp = g_v + ((size_t)bh * S_ + (j0 + n)) * DK + d0;
            #pragma unroll
            for (int q4 = 0; q4 < 4; ++q4)
                *reinterpret_cast<float4*>(&Vs[n * LDp + d0 + q4 * 4]) =
                    *reinterpret_cast<const float4*>(vp + q4 * 4);
        }
        __syncthreads();

        // ---- scores: St[j][m] = (Q K^T)[m][j] * SCALE ----
        {
            float sc[4][4] = {};
            #pragma unroll
            for (int kk = 0; kk < 64; ++kk) {
                float a[4], bb[4];
                *reinterpret_cast<float4*>(a)  = *reinterpret_cast<const float4*>(&Qs[kk * LDp + ty * 4]);
                *reinterpret_cast<float4*>(bb) = *reinterpret_cast<const float4*>(&Ks[kk * LDp + tx * 4]);
                #pragma unroll
                for (int i = 0; i < 4; ++i)
                    #pragma unroll
                    for (int j = 0; j < 4; ++j)
                        sc[i][j] = fmaf(a[i], bb[j], sc[i][j]);
            }
            #pragma unroll
            for (int j = 0; j < 4; ++j) {
                float4 v = make_float4(sc[0][j] * SCALE, sc[1][j] * SCALE,
                                       sc[2][j] * SCALE, sc[3][j] * SCALE);
                *reinterpret_cast<float4*>(&St[(tx * 4 + j) * LDp + ty * 4]) = v;
            }
        }
        __syncthreads();

        // ---- online softmax, one thread per query row ----
        if (tid < 64) {
            int r = tid;
            float mo = mrow[r];
            float mn = mo;
            #pragma unroll 8
            for (int j = 0; j < 64; ++j) mn = fmaxf(mn, St[j * LDp + r]);
            float al = __expf(mo - mn);
            float sum = 0.f;
            #pragma unroll 8
            for (int j = 0; j < 64; ++j) {
                float p = __expf(St[j * LDp + r] - mn);
                St[j * LDp + r] = p;
                sum += p;
            }
            lrow[r] = lrow[r] * al + sum;
            mrow[r] = mn;
            arow[r] = al;
        }
        __syncthreads();

        // ---- O = O*alpha + P @ V ----
        {
            float al[4];
            #pragma unroll
            for (int i = 0; i < 4; ++i) al[i] = arow[ty * 4 + i];
            #pragma unroll
            for (int i = 0; i < 4; ++i)
                #pragma unroll
                for (int j = 0; j < 4; ++j)
                    o[i][j] *= al[i];
            #pragma unroll
            for (int jj = 0; jj < 64; ++jj) {
                float a[4], bb[4];
                *reinterpret_cast<float4*>(a)  = *reinterpret_cast<const float4*>(&St[jj * LDp + ty * 4]);
                *reinterpret_cast<float4*>(bb) = *reinterpret_cast<const float4*>(&Vs[jj * LDp + tx * 4]);
                #pragma unroll
                for (int i = 0; i < 4; ++i)
                    #pragma unroll
                    for (int j = 0; j < 4; ++j)
                        o[i][j] = fmaf(a[i], bb[j], o[i][j]);
            }
        }
    }

    // ---- normalize + write res[b, s, h*64+d] ----
    #pragma unroll
    for (int i = 0; i < 4; ++i) {
        int s = s0 + ty * 4 + i;
        float inv = 1.0f / lrow[ty * 4 + i];
        float* rp = g_res + ((size_t)b * S_ + s) * C_ + h * 64 + tx * 4;
        float4 v = make_float4(o[i][0] * inv, o[i][1] * inv, o[i][2] * inv, o[i][3] * inv);
        *reinterpret_cast<float4*>(rp) = v;
    }
}

// ============================================================
// Kernel C: out = res @ w_out + b_out + xs, then transpose to [B,C,S]
// M=16384 (b,s), K=256 (hd), N=256 (c)
// ============================================================
__global__ void out_gemm(const float* __restrict__ x,
                         const float* __restrict__ w,
                         const float* __restrict__ bias,
                         float* __restrict__ out)
{
    __shared__ float As[16][68];   // [k][m] transposed
    __shared__ float Bs[16][64];   // [k][n]

    const int mBase = blockIdx.y * 64;
    const int nBase = blockIdx.x * 64;
    const int tid = threadIdx.x;
    const int tx = tid & 15, ty = tid >> 4;

    const int b  = mBase >> 10;
    const int s0 = mBase & 1023;

    float acc[4][4] = {};

    for (int k0 = 0; k0 < C_; k0 += 16) {
        {   // res[m][k] contiguous in k; transpose into As[k][m]
            int mi  = tid >> 2;
            int kk0 = (tid & 3) * 4;
            float4 v = *reinterpret_cast<const float4*>(
                g_res + (size_t)(mBase + mi) * C_ + k0 + kk0);
            As[kk0 + 0][mi] = v.x;
            As[kk0 + 1][mi] = v.y;
            As[kk0 + 2][mi] = v.z;
            As[kk0 + 3][mi] = v.w;
        }
        {
            int e  = tid * 4;
            int kk = e >> 6, ni = e & 63;
            const float* wp = w + (size_t)(k0 + kk) * C_ + nBase + ni;
            *reinterpret_cast<float4*>(&Bs[kk][ni]) =
                *reinterpret_cast<const float4*>(wp);
        }
        __syncthreads();
        #pragma unroll
        for (int kk = 0; kk < 16; ++kk) {
            float a[4], bb[4];
            *reinterpret_cast<float4*>(a)  = *reinterpret_cast<const float4*>(&As[kk][ty * 4]);
            *reinterpret_cast<float4*>(bb) = *reinterpret_cast<const float4*>(&Bs[kk][tx * 4]);
            #pragma unroll
            for (int i = 0; i < 4; ++i)
                #pragma unroll
                for (int j = 0; j < 4; ++j)
                    acc[i][j] = fmaf(a[i], bb[j], acc[i][j]);
        }
        __syncthreads();
    }

    // out[b][c][s] = acc + b_out[c] + x[b][c][s]
    #pragma unroll
    for (int j = 0; j < 4; ++j) {
        int c = nBase + tx * 4 + j;
        float bv = bias[c];
        const float* xp = x + ((size_t)b * C_ + c) * S_;
        float* op = out + ((size_t)b * C_ + c) * S_;
        #pragma unroll
        for (int i = 0; i < 4; ++i) {
            int s = s0 + ty * 4 + i;
            op[s] = acc[i][j] + bv + xp[s];
        }
    }
}

// ============================================================
extern "C" void kernel_launch(void* const* d_in, const int* in_sizes, int n_in,
                              void* d_out, int out_size)
{
    const float* x     = (const float*)d_in[0];
    const float* w_qkv = (const float*)d_in[1];
    const float* b_qkv = (const float*)d_in[2];
    const float* w_out = (const float*)d_in[3];
    const float* b_out = (const float*)d_in[4];
    float* out = (float*)d_out;

    cudaFuncSetAttribute(flash_attn, cudaFuncAttributeMaxDynamicSharedMemorySize,
                         FLASH_SMEM);

    qkv_gemm<<<dim3(768 / 64, (B_ * S_) / 64), 256>>>(x, w_qkv, b_qkv);
    flash_attn<<<dim3(S_ / 64, B_ * NH), 256, FLASH_SMEM>>>();
    out_gemm<<<dim3(C_ / 64, (B_ * S_) / 64), 256>>>(x, w_out, b_out, out);
}